// round 4
// baseline (speedup 1.0000x reference)
#include <cuda_runtime.h>
#include <cuda_bf16.h>

// Pillar scatter, gather-formulated, v2.
// out[b,f,y,x] = sum_{p: mask[b,p]==1, coord[b,p,1:3]==(y,x)} pillars[b,p,f]
// B=4, P=12000, NF=64, grid 512x512. Output 268 MB fp32.
//
// v2 fix vs v1: one thread owns 4 cells for ALL 64 features, so the count
// grid (4 MB) is read ONCE, not once per feature plane (v1 burned 256 MB of
// L2 traffic re-reading it — LTS cap is path-independent).
//
//  1) reset:  zero count grid (4 MB) + overflow counter
//  2) count:  active pillars register into per-cell slot lists (K=8)
//  3) fill:   one streaming pass over the 268 MB output; coalesced float4
//             stores; nonzero cells gather from L1/L2-resident pillar rows
//  4) ovf:    atomic fixup for >K-pillar cells (statistically empty)

#define XS 512
#define GRID_CELLS (XS * XS)   // 262144 = 2^18
#define BMAX 4
#define NFC 64
#define K 8
#define OVF_CAP 4096

__device__ __align__(16) int d_count[BMAX * GRID_CELLS];
__device__ int d_slots[BMAX * GRID_CELLS * K];
__device__ int d_ovf_n;
__device__ int d_ovf[OVF_CAP * 2];

__global__ void reset_kernel(int n_int4) {
    int i = blockIdx.x * blockDim.x + threadIdx.x;
    if (i == 0) d_ovf_n = 0;
    if (i < n_int4)
        reinterpret_cast<int4*>(d_count)[i] = make_int4(0, 0, 0, 0);
}

__global__ void count_kernel(const int* __restrict__ coord,
                             const int* __restrict__ mask,
                             int BP, int P) {
    int i = blockIdx.x * blockDim.x + threadIdx.x;
    if (i >= BP) return;
    if (mask[i] == 0) return;
    int y = coord[i * 3 + 1];
    int x = coord[i * 3 + 2];
    int b = i / P;
    int cell = b * GRID_CELLS + y * XS + x;
    int pos = atomicAdd(&d_count[cell], 1);
    if (pos < K) {
        d_slots[cell * K + pos] = i;          // global pillar index
    } else {
        int o = atomicAdd(&d_ovf_n, 1);
        if (o < OVF_CAP) { d_ovf[o * 2] = i; d_ovf[o * 2 + 1] = cell; }
    }
}

// One thread per 4 grid cells, covering ALL NFC feature planes.
// nthreads = B * GRID_CELLS / 4 = 262144.
// Output plane stride in float4 units = GRID_CELLS/4 = 65536.
__global__ void fill_kernel(const float* __restrict__ pillars,
                            float4* __restrict__ out, int nthreads) {
    int tid = blockIdx.x * blockDim.x + threadIdx.x;
    if (tid >= nthreads) return;
    int yx4 = tid & (GRID_CELLS / 4 - 1);          // 2^16 - 1
    int b   = tid >> 16;

    int cellbase = b * GRID_CELLS + (yx4 << 2);
    int4 c = *reinterpret_cast<const int4*>(&d_count[cellbase]);

    float4* obase = out + ((long)b * NFC) * (GRID_CELLS / 4) + yx4;

    if ((c.x | c.y | c.z | c.w) == 0) {
        // ~91% of threads: pure coalesced zero stream, high MLP.
        float4 z = make_float4(0.f, 0.f, 0.f, 0.f);
        #pragma unroll 16
        for (int f = 0; f < NFC; f++)
            obase[f << 16] = z;
    } else {
        int n0 = min(c.x, K), n1 = min(c.y, K);
        int n2 = min(c.z, K), n3 = min(c.w, K);
        const int* s0 = &d_slots[(cellbase + 0) * K];
        const int* s1 = &d_slots[(cellbase + 1) * K];
        const int* s2 = &d_slots[(cellbase + 2) * K];
        const int* s3 = &d_slots[(cellbase + 3) * K];
        #pragma unroll 4
        for (int f = 0; f < NFC; f++) {
            float4 v = make_float4(0.f, 0.f, 0.f, 0.f);
            for (int s = 0; s < n0; s++) v.x += pillars[(long)s0[s] * NFC + f];
            for (int s = 0; s < n1; s++) v.y += pillars[(long)s1[s] * NFC + f];
            for (int s = 0; s < n2; s++) v.z += pillars[(long)s2[s] * NFC + f];
            for (int s = 0; s < n3; s++) v.w += pillars[(long)s3[s] * NFC + f];
            obase[f << 16] = v;
        }
    }
}

__global__ void ovf_kernel(const float* __restrict__ pillars,
                           float* __restrict__ out) {
    int n = min(d_ovf_n, OVF_CAP);
    for (int i = 0; i < n; i++) {                  // rare path; serial is fine
        int pg   = d_ovf[i * 2];
        int cell = d_ovf[i * 2 + 1];
        int b  = cell >> 18;
        int yx = cell & (GRID_CELLS - 1);
        for (int f = threadIdx.x; f < NFC; f += blockDim.x)
            atomicAdd(out + (long)b * NFC * GRID_CELLS + (long)f * GRID_CELLS + yx,
                      pillars[(long)pg * NFC + f]);
    }
}

extern "C" void kernel_launch(void* const* d_in, const int* in_sizes, int n_in,
                              void* d_out, int out_size) {
    const float* pillars = (const float*)d_in[0];   // [B, P, NF]
    const int*   coord   = (const int*)d_in[1];     // [B, P, 3]
    const int*   mask    = (const int*)d_in[2];     // [B, P]

    int BP = in_sizes[2];                           // B * P = 48000
    int B  = (int)((long)out_size / ((long)NFC * GRID_CELLS));
    int P  = BP / B;
    float* out = (float*)d_out;

    int n_int4 = (B * GRID_CELLS) / 4;
    reset_kernel<<<(n_int4 + 511) / 512, 512>>>(n_int4);

    count_kernel<<<(BP + 255) / 256, 256>>>(coord, mask, BP, P);

    int nthreads = B * GRID_CELLS / 4;              // 262144
    fill_kernel<<<(nthreads + 255) / 256, 256>>>(pillars, (float4*)out, nthreads);

    ovf_kernel<<<1, 64>>>(pillars, out);
}

// round 5
// speedup vs baseline: 1.4245x; 1.4245x over previous
#include <cuda_runtime.h>
#include <cuda_bf16.h>

// Pillar scatter v3: streaming zero + plain-store paint (no atomics on out).
// out[b,f,y,x] = sum_{p: mask[b,p]==1, coord[b,p,1:3]==(y,x)} pillars[b,p,f]
// B=4, P=12000, NF=64, grid 512x512, output 268 MB fp32.
//
//  1) reset: zero 4 MB count grid + counters
//  2) count: bin active pillars into per-cell slot lists; first toucher of a
//            cell appends it to a compact touched-cell list
//  3) zero:  linear grid-stride float4 zero of the full output (proven
//            streaming pattern, ~5.7 TB/s) — NO per-cell branching
//  4) paint: one warp per touched cell; sum its slot list (collisions
//            resolved here), plain coalesced-read / scattered-store of the
//            final 64 feature values. Overflow (>K) handled inline by the
//            owning warp via the ovf side list (statistically never taken).

#define XS 512
#define GRID_CELLS (XS * XS)   // 262144 = 2^18
#define BMAX 4
#define NFC 64
#define K 8
#define OVF_CAP 4096

__device__ __align__(16) int d_count[BMAX * GRID_CELLS];
__device__ int d_slots[BMAX * GRID_CELLS * K];
__device__ int d_touched[BMAX * 12000];
__device__ int d_touched_n;
__device__ int d_ovf_n;
__device__ int d_ovf[OVF_CAP * 2];   // (pillar, cell) pairs

__global__ void reset_kernel(int n_int4) {
    int i = blockIdx.x * blockDim.x + threadIdx.x;
    if (i == 0) { d_touched_n = 0; d_ovf_n = 0; }
    if (i < n_int4)
        reinterpret_cast<int4*>(d_count)[i] = make_int4(0, 0, 0, 0);
}

__global__ void count_kernel(const int* __restrict__ coord,
                             const int* __restrict__ mask,
                             int BP, int P) {
    int i = blockIdx.x * blockDim.x + threadIdx.x;
    if (i >= BP) return;
    if (mask[i] == 0) return;
    int y = coord[i * 3 + 1];
    int x = coord[i * 3 + 2];
    int b = i / P;
    int cell = b * GRID_CELLS + y * XS + x;
    int pos = atomicAdd(&d_count[cell], 1);
    if (pos < K) {
        d_slots[cell * K + pos] = i;              // global pillar index
    } else {
        int o = atomicAdd(&d_ovf_n, 1);
        if (o < OVF_CAP) { d_ovf[o * 2] = i; d_ovf[o * 2 + 1] = cell; }
    }
    if (pos == 0) {
        int t = atomicAdd(&d_touched_n, 1);
        d_touched[t] = cell;
    }
}

// Pure streaming zero: linear float4 grid-stride, no branching.
__global__ void zero_kernel(float4* __restrict__ out, int n4) {
    int i = blockIdx.x * blockDim.x + threadIdx.x;
    int stride = gridDim.x * blockDim.x;
    float4 z = make_float4(0.f, 0.f, 0.f, 0.f);
    for (; i < n4; i += stride)
        out[i] = z;
}

// One warp per touched cell. Reads slot pillar rows coalesced (256 B each),
// writes 64 final feature values with plain scattered STG.32 (no RMW read).
__global__ void paint_kernel(const float* __restrict__ pillars,
                             float* __restrict__ out) {
    int n = d_touched_n;
    int w = (int)((blockIdx.x * (long)blockDim.x + threadIdx.x) >> 5);
    if (w >= n) return;
    int lane = threadIdx.x & 31;

    int cell = d_touched[w];
    int cnt_raw = d_count[cell];
    int cnt = min(cnt_raw, K);

    float v0 = 0.f, v1 = 0.f;
    for (int s = 0; s < cnt; s++) {
        const float* row = pillars + (long)d_slots[cell * K + s] * NFC;
        v0 += row[lane];
        v1 += row[lane + 32];
    }

    if (cnt_raw > K) {                            // ~never; correctness only
        int no = min(d_ovf_n, OVF_CAP);
        for (int o = 0; o < no; o++) {
            if (d_ovf[o * 2 + 1] == cell) {
                const float* row = pillars + (long)d_ovf[o * 2] * NFC;
                v0 += row[lane];
                v1 += row[lane + 32];
            }
        }
    }

    int b  = cell >> 18;                          // / GRID_CELLS
    int yx = cell & (GRID_CELLS - 1);
    float* obase = out + (long)b * NFC * GRID_CELLS + yx;
    obase[(long)lane * GRID_CELLS] = v0;
    obase[(long)(lane + 32) * GRID_CELLS] = v1;
}

extern "C" void kernel_launch(void* const* d_in, const int* in_sizes, int n_in,
                              void* d_out, int out_size) {
    const float* pillars = (const float*)d_in[0];   // [B, P, NF]
    const int*   coord   = (const int*)d_in[1];     // [B, P, 3]
    const int*   mask    = (const int*)d_in[2];     // [B, P]

    int BP = in_sizes[2];                           // B * P = 48000
    int B  = (int)((long)out_size / ((long)NFC * GRID_CELLS));
    int P  = BP / B;
    float* out = (float*)d_out;

    int n_int4 = (B * GRID_CELLS) / 4;
    reset_kernel<<<(n_int4 + 511) / 512, 512>>>(n_int4);

    count_kernel<<<(BP + 255) / 256, 256>>>(coord, mask, BP, P);

    int n4 = out_size / 4;
    zero_kernel<<<2368, 256>>>((float4*)out, n4);

    // Worst case: every active pillar owns a distinct cell -> BP warps.
    int paint_blocks = (BP * 32 + 255) / 256;       // 6000
    paint_kernel<<<paint_blocks, 256>>>(pillars, out);
}

// round 6
// speedup vs baseline: 1.4303x; 1.0041x over previous
#include <cuda_runtime.h>
#include <cuda_bf16.h>

// Pillar scatter v3: streaming zero + plain-store paint (no atomics on out).
// out[b,f,y,x] = sum_{p: mask[b,p]==1, coord[b,p,1:3]==(y,x)} pillars[b,p,f]
// B=4, P=12000, NF=64, grid 512x512, output 268 MB fp32.
//
//  1) reset: zero 4 MB count grid + counters
//  2) count: bin active pillars into per-cell slot lists; first toucher of a
//            cell appends it to a compact touched-cell list
//  3) zero:  linear grid-stride float4 zero of the full output (proven
//            streaming pattern, ~5.7 TB/s) — NO per-cell branching
//  4) paint: one warp per touched cell; sum its slot list (collisions
//            resolved here), plain coalesced-read / scattered-store of the
//            final 64 feature values. Overflow (>K) handled inline by the
//            owning warp via the ovf side list (statistically never taken).

#define XS 512
#define GRID_CELLS (XS * XS)   // 262144 = 2^18
#define BMAX 4
#define NFC 64
#define K 8
#define OVF_CAP 4096

__device__ __align__(16) int d_count[BMAX * GRID_CELLS];
__device__ int d_slots[BMAX * GRID_CELLS * K];
__device__ int d_touched[BMAX * 12000];
__device__ int d_touched_n;
__device__ int d_ovf_n;
__device__ int d_ovf[OVF_CAP * 2];   // (pillar, cell) pairs

__global__ void reset_kernel(int n_int4) {
    int i = blockIdx.x * blockDim.x + threadIdx.x;
    if (i == 0) { d_touched_n = 0; d_ovf_n = 0; }
    if (i < n_int4)
        reinterpret_cast<int4*>(d_count)[i] = make_int4(0, 0, 0, 0);
}

__global__ void count_kernel(const int* __restrict__ coord,
                             const int* __restrict__ mask,
                             int BP, int P) {
    int i = blockIdx.x * blockDim.x + threadIdx.x;
    if (i >= BP) return;
    if (mask[i] == 0) return;
    int y = coord[i * 3 + 1];
    int x = coord[i * 3 + 2];
    int b = i / P;
    int cell = b * GRID_CELLS + y * XS + x;
    int pos = atomicAdd(&d_count[cell], 1);
    if (pos < K) {
        d_slots[cell * K + pos] = i;              // global pillar index
    } else {
        int o = atomicAdd(&d_ovf_n, 1);
        if (o < OVF_CAP) { d_ovf[o * 2] = i; d_ovf[o * 2 + 1] = cell; }
    }
    if (pos == 0) {
        int t = atomicAdd(&d_touched_n, 1);
        d_touched[t] = cell;
    }
}

// Pure streaming zero: linear float4 grid-stride, no branching.
__global__ void zero_kernel(float4* __restrict__ out, int n4) {
    int i = blockIdx.x * blockDim.x + threadIdx.x;
    int stride = gridDim.x * blockDim.x;
    float4 z = make_float4(0.f, 0.f, 0.f, 0.f);
    for (; i < n4; i += stride)
        out[i] = z;
}

// One warp per touched cell. Reads slot pillar rows coalesced (256 B each),
// writes 64 final feature values with plain scattered STG.32 (no RMW read).
__global__ void paint_kernel(const float* __restrict__ pillars,
                             float* __restrict__ out) {
    int n = d_touched_n;
    int w = (int)((blockIdx.x * (long)blockDim.x + threadIdx.x) >> 5);
    if (w >= n) return;
    int lane = threadIdx.x & 31;

    int cell = d_touched[w];
    int cnt_raw = d_count[cell];
    int cnt = min(cnt_raw, K);

    float v0 = 0.f, v1 = 0.f;
    for (int s = 0; s < cnt; s++) {
        const float* row = pillars + (long)d_slots[cell * K + s] * NFC;
        v0 += row[lane];
        v1 += row[lane + 32];
    }

    if (cnt_raw > K) {                            // ~never; correctness only
        int no = min(d_ovf_n, OVF_CAP);
        for (int o = 0; o < no; o++) {
            if (d_ovf[o * 2 + 1] == cell) {
                const float* row = pillars + (long)d_ovf[o * 2] * NFC;
                v0 += row[lane];
                v1 += row[lane + 32];
            }
        }
    }

    int b  = cell >> 18;                          // / GRID_CELLS
    int yx = cell & (GRID_CELLS - 1);
    float* obase = out + (long)b * NFC * GRID_CELLS + yx;
    obase[(long)lane * GRID_CELLS] = v0;
    obase[(long)(lane + 32) * GRID_CELLS] = v1;
}

extern "C" void kernel_launch(void* const* d_in, const int* in_sizes, int n_in,
                              void* d_out, int out_size) {
    const float* pillars = (const float*)d_in[0];   // [B, P, NF]
    const int*   coord   = (const int*)d_in[1];     // [B, P, 3]
    const int*   mask    = (const int*)d_in[2];     // [B, P]

    int BP = in_sizes[2];                           // B * P = 48000
    int B  = (int)((long)out_size / ((long)NFC * GRID_CELLS));
    int P  = BP / B;
    float* out = (float*)d_out;

    int n_int4 = (B * GRID_CELLS) / 4;
    reset_kernel<<<(n_int4 + 511) / 512, 512>>>(n_int4);

    count_kernel<<<(BP + 255) / 256, 256>>>(coord, mask, BP, P);

    int n4 = out_size / 4;
    zero_kernel<<<2368, 256>>>((float4*)out, n4);

    // Worst case: every active pillar owns a distinct cell -> BP warps.
    int paint_blocks = (BP * 32 + 255) / 256;       // 6000
    paint_kernel<<<paint_blocks, 256>>>(pillars, out);
}